// round 10
// baseline (speedup 1.0000x reference)
#include <cuda_runtime.h>
#include <math.h>

#define B_ 8
#define S_ 1024
#define D_ 512
#define H_ 8
#define DK_ 64

#define TM 32
#define BJ 256
#define SS_STRIDE 1032
#define SQ_STRIDE 68
#define SKT_STRIDE 264
#define SV_STRIDE 68
#define KVBUF 17408   // max(64*264, 256*68)

// scratch (device globals; no allocation allowed)
__device__ float g_qk[B_*H_*S_*DK_];   // 16 MB, q == k (kq_same)
__device__ float g_v [B_*H_*S_*DK_];   // 16 MB
__device__ float g_attn[B_*S_*D_];     // 16 MB

// ---------------------------------------------------------------------------
// Kernel 1: fused QK / V projection (scalar FFMA at issue roofline).
// ---------------------------------------------------------------------------
__global__ __launch_bounds__(256) void proj_kernel(
    const float* __restrict__ x,
    const float* __restrict__ Wk, const float* __restrict__ bk,
    const float* __restrict__ Wv, const float* __restrict__ bv)
{
    __shared__ float sA[16*68];
    __shared__ float sB[16*68];

    const float* W    = blockIdx.z ? Wv : Wk;
    const float* bias = blockIdx.z ? bv : bk;
    float* dst        = blockIdx.z ? g_v : g_qk;

    const int m0 = blockIdx.y * 64;
    const int n0 = blockIdx.x * 64;
    const int tid = threadIdx.x;
    const int tx = tid & 15;
    const int ty = tid >> 4;
    const int lrow = tid >> 2;
    const int lc4  = tid & 3;

    float acc[4][4] = {};

    for (int k0 = 0; k0 < D_; k0 += 16) {
        float4 av = *(const float4*)(x + (long)(m0 + lrow)*D_ + k0 + lc4*4);
        float4 bw = *(const float4*)(W + (long)(n0 + lrow)*D_ + k0 + lc4*4);
        __syncthreads();
        sA[(lc4*4+0)*68 + lrow] = av.x;
        sA[(lc4*4+1)*68 + lrow] = av.y;
        sA[(lc4*4+2)*68 + lrow] = av.z;
        sA[(lc4*4+3)*68 + lrow] = av.w;
        sB[(lc4*4+0)*68 + lrow] = bw.x;
        sB[(lc4*4+1)*68 + lrow] = bw.y;
        sB[(lc4*4+2)*68 + lrow] = bw.z;
        sB[(lc4*4+3)*68 + lrow] = bw.w;
        __syncthreads();
        #pragma unroll
        for (int kk = 0; kk < 16; ++kk) {
            float4 a4 = *(const float4*)(sA + kk*68 + ty*4);
            float4 b4 = *(const float4*)(sB + kk*68 + tx*4);
            acc[0][0] += a4.x*b4.x; acc[0][1] += a4.x*b4.y; acc[0][2] += a4.x*b4.z; acc[0][3] += a4.x*b4.w;
            acc[1][0] += a4.y*b4.x; acc[1][1] += a4.y*b4.y; acc[1][2] += a4.y*b4.z; acc[1][3] += a4.y*b4.w;
            acc[2][0] += a4.z*b4.x; acc[2][1] += a4.z*b4.y; acc[2][2] += a4.z*b4.z; acc[2][3] += a4.z*b4.w;
            acc[3][0] += a4.w*b4.x; acc[3][1] += a4.w*b4.y; acc[3][2] += a4.w*b4.z; acc[3][3] += a4.w*b4.w;
        }
    }

    const int n = n0 + tx*4;
    const int hh = n >> 6;
    const int dd = n & 63;
    float4 bia = *(const float4*)(bias + n);
    #pragma unroll
    for (int r = 0; r < 4; ++r) {
        int m = m0 + ty*4 + r;
        int bb = m >> 10, ss = m & 1023;
        float4 v;
        v.x = acc[r][0] + bia.x;
        v.y = acc[r][1] + bia.y;
        v.z = acc[r][2] + bia.z;
        v.w = acc[r][3] + bia.w;
        *(float4*)(dst + (((long)bb*H_ + hh)*S_ + ss)*DK_ + dd) = v;
    }
}

// ---------------------------------------------------------------------------
// Kernel 2: attention with distance decay.  One block = 32 query rows of one
// (b,h), 512 threads.  No max-subtraction (scores bounded); two-level scan
// (independent chunk sums + warp scan of chunk sums -> no serial carry).
// ---------------------------------------------------------------------------
__global__ __launch_bounds__(512) void attn_kernel(
    const float* __restrict__ utT, const float* __restrict__ gammas)
{
    extern __shared__ float smem[];
    float* sS   = smem;                       // 32*1032
    float* sQ   = sS  + TM*SS_STRIDE;         // 32*68
    float* sKV  = sQ  + TM*SQ_STRIDE;         // KVBUF (K^T or V tile)
    float* sInv = sKV + KVBUF;                // 32
    float* sCS  = sInv + 32;                  // 32 rows * 33 chunk sums

    const int i0 = blockIdx.x * TM;
    const int h  = blockIdx.y;
    const int b  = blockIdx.z;
    const int tid = threadIdx.x;
    const long bh = (long)(b*H_ + h);
    const float* Kbase = g_qk + bh*(long)(S_*DK_);
    const float* Vbase = g_v  + bh*(long)(S_*DK_);
    const int TJn  = (i0 + TM + BJ - 1) / BJ;
    const int JMAX = TJn * BJ;

    // ---- load Q tile (32 x 64) ----
    {
        int row = tid >> 4, c4 = (tid & 15)*4;
        float4 v = *(const float4*)(Kbase + (long)(i0+row)*DK_ + c4);
        *(float4*)(sQ + row*SQ_STRIDE + c4) = v;
    }

    // ---- score GEMM: sS[i][j] = (q_i . k_j)/8 * utT[b,i,j] ----
    const int tx = tid & 63;    // 64 groups x 4 cols
    const int ty = tid >> 6;    // 8 groups x 4 rows
    const float kscale = 0.125f;

    for (int jt=0; jt<TJn; ++jt){
        const int j0 = jt*BJ;
        __syncthreads();
        // K^T with XOR swizzle: element k_j[k] at sKV[k*264 + (j ^ (k&60))]
        #pragma unroll
        for (int it=0; it<8; ++it){
            int idx = tid + it*512;
            int jrow = idx >> 4;
            int c4   = (idx & 15)*4;
            float4 v = *(const float4*)(Kbase + (long)(j0+jrow)*DK_ + c4);
            int js = jrow ^ c4;
            sKV[(c4+0)*SKT_STRIDE + js] = v.x;
            sKV[(c4+1)*SKT_STRIDE + js] = v.y;
            sKV[(c4+2)*SKT_STRIDE + js] = v.z;
            sKV[(c4+3)*SKT_STRIDE + js] = v.w;
        }
        __syncthreads();

        float acc[4][4] = {};
        #pragma unroll
        for (int kkc=0; kkc<16; ++kkc){
            const int cb = (tx*4) ^ (kkc*4);
            const float* kb = sKV + (kkc*4)*SKT_STRIDE + cb;
            float4 k0 = *(const float4*)(kb);
            float4 k1 = *(const float4*)(kb + SKT_STRIDE);
            float4 k2 = *(const float4*)(kb + 2*SKT_STRIDE);
            float4 k3 = *(const float4*)(kb + 3*SKT_STRIDE);
            #pragma unroll
            for (int r=0; r<4; ++r){
                float4 q = *(const float4*)(sQ + (ty*4+r)*SQ_STRIDE + kkc*4);
                acc[r][0] += q.x*k0.x + q.y*k1.x + q.z*k2.x + q.w*k3.x;
                acc[r][1] += q.x*k0.y + q.y*k1.y + q.z*k2.y + q.w*k3.y;
                acc[r][2] += q.x*k0.z + q.y*k1.z + q.z*k2.z + q.w*k3.z;
                acc[r][3] += q.x*k0.w + q.y*k1.w + q.z*k2.w + q.w*k3.w;
            }
        }

        const int jl = j0 + tx*4;
        #pragma unroll
        for (int r=0; r<4; ++r){
            int gi = i0 + ty*4 + r;
            float4 u4 = *(const float4*)(utT + ((long)b*S_ + gi)*S_ + jl);
            float4 w;
            w.x = acc[r][0]*kscale*u4.x;
            w.y = acc[r][1]*kscale*u4.y;
            w.z = acc[r][2]*kscale*u4.z;
            w.w = acc[r][3]*kscale*u4.w;
            *(float4*)(sS + (ty*4+r)*SS_STRIDE + jl) = w;
        }
    }
    __syncthreads();

    // ---- softmax1 -> cumsum -> decay -> exp2 (no max; two-level scan) ----
    {
        const int wid = tid >> 5, lane = tid & 31;   // 16 warps x 2 rows
        const unsigned FULL = 0xffffffffu;
        const float gh = -log1pf(__expf(gammas[h]));

        #pragma unroll 1
        for (int q=0; q<2; ++q){
            int r  = wid*2 + q;
            int gi = i0 + r;
            int L  = gi + 1;
            float* row = sS + r*SS_STRIDE;
            int nch = (L + 31) >> 5;

            // pass 1: independent chunk sums of exp(s)
            #pragma unroll 2
            for (int c = 0; c < nch; ++c){
                int j = c*32 + lane;
                float e = (j < L) ? __expf(row[j]) : 0.f;
                #pragma unroll
                for (int o=16;o>0;o>>=1) e += __shfl_xor_sync(FULL, e, o);
                if (lane == 0) sCS[r*33 + c] = e;
            }
            // zero tail for the out-GEMM
            for (int j = L + lane; j < JMAX; j += 32) row[j] = 0.f;

            // warp scan over chunk sums -> exclusive chunk prefixes + total
            float cs = (lane < nch) ? sCS[r*33 + lane] : 0.f;
            float incl = cs;
            #pragma unroll
            for (int o=1;o<32;o<<=1){
                float t = __shfl_up_sync(FULL, incl, o);
                if (lane >= o) incl += t;
            }
            float excl = incl - cs;
            float sm   = __shfl_sync(FULL, incl, 31);
            float inv  = 1.f / sm;

            // pass 2: intra-chunk scan (no inter-chunk carry), decay, exp2
            float sm2 = 0.f;
            #pragma unroll 2
            for (int c = 0; c < nch; ++c){
                int j = c*32 + lane;
                bool in = j < L;
                float s = in ? row[j] : 0.f;
                float e = in ? __expf(s) : 0.f;
                float v = e;
                #pragma unroll
                for (int o=1;o<32;o<<=1){
                    float t = __shfl_up_sync(FULL, v, o);
                    if (lane >= o) v += t;
                }
                float cum = __shfl_sync(FULL, excl, c) + v;
                float rem = fmaxf(0.f, (sm - cum) * inv);
                float y   = rem * (float)(gi - j);
                float dist = (y > 0.f) ? y * __frsqrt_rn(y) : 0.f;
                float te = fmaxf(__expf(dist * gh), 1e-5f);
                float e2 = in ? __expf(s * te) : 0.f;
                if (in) row[j] = e2;
                sm2 += e2;
            }
            #pragma unroll
            for (int o=16;o>0;o>>=1) sm2 += __shfl_xor_sync(FULL, sm2, o);
            if (lane == 0) sInv[r] = 1.f / sm2;
        }
    }

    // ---- out GEMM: out[i][d] = sInv[i] * sum_j e2[i][j] * v[j][d] ----
    {
        const int rg = tid >> 4;        // 32 rows
        const int dg = tid & 15;        // 16 x 4 d-cols
        float a0=0.f, a1=0.f, a2=0.f, a3=0.f;

        for (int jt=0; jt<TJn; ++jt){
            const int j0 = jt*BJ;
            __syncthreads();
            #pragma unroll
            for (int it=0; it<8; ++it){
                int idx = tid + it*512;
                int row = idx >> 4, c4 = (idx & 15)*4;
                float4 v = *(const float4*)(Vbase + (long)(j0+row)*DK_ + c4);
                *(float4*)(sKV + row*SV_STRIDE + c4) = v;
            }
            __syncthreads();
            const float* prow = sS + rg*SS_STRIDE + j0;
            #pragma unroll 2
            for (int jj=0; jj<BJ; jj+=4){
                float4 p4 = *(const float4*)(prow + jj);
                const float* vb = sKV + jj*SV_STRIDE + dg*4;
                float4 v0 = *(const float4*)(vb);
                float4 v1 = *(const float4*)(vb + SV_STRIDE);
                float4 v2 = *(const float4*)(vb + 2*SV_STRIDE);
                float4 v3 = *(const float4*)(vb + 3*SV_STRIDE);
                a0 += p4.x*v0.x + p4.y*v1.x + p4.z*v2.x + p4.w*v3.x;
                a1 += p4.x*v0.y + p4.y*v1.y + p4.z*v2.y + p4.w*v3.y;
                a2 += p4.x*v0.z + p4.y*v1.z + p4.z*v2.z + p4.w*v3.z;
                a3 += p4.x*v0.w + p4.y*v1.w + p4.z*v2.w + p4.w*v3.w;
            }
        }

        float sc = sInv[rg];
        float4 w; w.x=a0*sc; w.y=a1*sc; w.z=a2*sc; w.w=a3*sc;
        *(float4*)(g_attn + ((long)b*S_ + i0 + rg)*D_ + h*DK_ + dg*4) = w;
    }
}

// ---------------------------------------------------------------------------
// Kernel 3: output projection.  out = g_attn @ Wo^T + bo.
// ---------------------------------------------------------------------------
__global__ __launch_bounds__(256) void out_kernel(
    const float* __restrict__ Wo, const float* __restrict__ bo,
    float* __restrict__ out)
{
    __shared__ float sA[16*68];
    __shared__ float sB[16*68];

    const int m0 = blockIdx.y * 64;
    const int n0 = blockIdx.x * 64;
    const int tid = threadIdx.x;
    const int tx = tid & 15;
    const int ty = tid >> 4;
    const int lrow = tid >> 2;
    const int lc4  = tid & 3;

    float acc[4][4] = {};

    for (int k0 = 0; k0 < D_; k0 += 16) {
        float4 av = *(const float4*)(g_attn + (long)(m0 + lrow)*D_ + k0 + lc4*4);
        float4 bw = *(const float4*)(Wo     + (long)(n0 + lrow)*D_ + k0 + lc4*4);
        __syncthreads();
        sA[(lc4*4+0)*68 + lrow] = av.x;
        sA[(lc4*4+1)*68 + lrow] = av.y;
        sA[(lc4*4+2)*68 + lrow] = av.z;
        sA[(lc4*4+3)*68 + lrow] = av.w;
        sB[(lc4*4+0)*68 + lrow] = bw.x;
        sB[(lc4*4+1)*68 + lrow] = bw.y;
        sB[(lc4*4+2)*68 + lrow] = bw.z;
        sB[(lc4*4+3)*68 + lrow] = bw.w;
        __syncthreads();
        #pragma unroll
        for (int kk = 0; kk < 16; ++kk) {
            float4 a4 = *(const float4*)(sA + kk*68 + ty*4);
            float4 b4 = *(const float4*)(sB + kk*68 + tx*4);
            acc[0][0] += a4.x*b4.x; acc[0][1] += a4.x*b4.y; acc[0][2] += a4.x*b4.z; acc[0][3] += a4.x*b4.w;
            acc[1][0] += a4.y*b4.x; acc[1][1] += a4.y*b4.y; acc[1][2] += a4.y*b4.z; acc[1][3] += a4.y*b4.w;
            acc[2][0] += a4.z*b4.x; acc[2][1] += a4.z*b4.y; acc[2][2] += a4.z*b4.z; acc[2][3] += a4.z*b4.w;
            acc[3][0] += a4.w*b4.x; acc[3][1] += a4.w*b4.y; acc[3][2] += a4.w*b4.z; acc[3][3] += a4.w*b4.w;
        }
    }

    const int n = n0 + tx*4;
    float4 bia = *(const float4*)(bo + n);
    #pragma unroll
    for (int r = 0; r < 4; ++r) {
        int m = m0 + ty*4 + r;
        float4 v;
        v.x = acc[r][0] + bia.x;
        v.y = acc[r][1] + bia.y;
        v.z = acc[r][2] + bia.z;
        v.w = acc[r][3] + bia.w;
        *(float4*)(out + (long)m*D_ + n) = v;
    }
}

// ---------------------------------------------------------------------------
extern "C" void kernel_launch(void* const* d_in, const int* in_sizes, int n_in,
                              void* d_out, int out_size)
{
    const float* x      = (const float*)d_in[0];
    const float* utT    = (const float*)d_in[1];
    const float* Wk     = (const float*)d_in[2];
    const float* bk     = (const float*)d_in[3];
    const float* Wv     = (const float*)d_in[4];
    const float* bv     = (const float*)d_in[5];
    const float* Wo     = (const float*)d_in[6];
    const float* bo     = (const float*)d_in[7];
    const float* gammas = (const float*)d_in[8];
    float* out = (float*)d_out;

    // QK + V projections (z selects which weight)
    proj_kernel<<<dim3(D_/64, (B_*S_)/64, 2), 256>>>(x, Wk, bk, Wv, bv);

    // attention
    size_t smem_bytes = (size_t)(TM*SS_STRIDE + TM*SQ_STRIDE + KVBUF + 32 + 32*33) * sizeof(float);
    cudaFuncSetAttribute(attn_kernel, cudaFuncAttributeMaxDynamicSharedMemorySize, (int)smem_bytes);
    attn_kernel<<<dim3(S_/TM, H_, B_), 512, smem_bytes>>>(utT, gammas);

    // output projection
    out_kernel<<<dim3(D_/64, (B_*S_)/64), 256>>>(Wo, bo, out);
}

// round 13
// speedup vs baseline: 1.1020x; 1.1020x over previous
#include <cuda_runtime.h>
#include <math.h>
#include <stdint.h>

#define B_ 8
#define S_ 1024
#define D_ 512
#define H_ 8
#define DK_ 64

#define TM 32
#define BJ 256
#define SS_STRIDE 1032
#define SQ_STRIDE 68
#define SKT_STRIDE 264
#define SV_STRIDE 68
#define KVBUF 17408   // max(64*264, 256*68)

// scratch (device globals; no allocation allowed)
__device__ float g_qk[B_*H_*S_*DK_];   // 16 MB, q == k (kq_same)
__device__ float g_v [B_*H_*S_*DK_];   // 16 MB
__device__ float g_attn[B_*S_*D_];     // 16 MB

// ---------------------------------------------------------------------------
// helpers
// ---------------------------------------------------------------------------
__device__ __forceinline__ float tf32_rd(float a){
    uint32_t u; asm("cvt.rna.tf32.f32 %0, %1;" : "=r"(u) : "f"(a));
    return __uint_as_float(u);
}
__device__ __forceinline__ void mma_tf32(float* c, const uint32_t* a, const uint32_t* b){
    asm volatile("mma.sync.aligned.m16n8k8.row.col.f32.tf32.tf32.f32 "
        "{%0,%1,%2,%3}, {%4,%5,%6,%7}, {%8,%9}, {%0,%1,%2,%3};"
        : "+f"(c[0]), "+f"(c[1]), "+f"(c[2]), "+f"(c[3])
        : "r"(a[0]), "r"(a[1]), "r"(a[2]), "r"(a[3]), "r"(b[0]), "r"(b[1]));
}

// ---------------------------------------------------------------------------
// Tensor-core 3xTF32 GEMM:  dst[M,N] = A[M,512] @ W[N,512]^T + bias
// Block tile 128x64, 8 warps (4m x 2n), K-chunks of 32, split in registers.
// ---------------------------------------------------------------------------
#define SA_STRIDE 36
__global__ __launch_bounds__(256) void gemm_mma(
    const float* __restrict__ A, const float* __restrict__ W,
    const float* __restrict__ bias, float* __restrict__ dst, int head_split)
{
    __shared__ float sA[128*SA_STRIDE];
    __shared__ float sW[64*SA_STRIDE];

    const int tid = threadIdx.x;
    const int wid = tid >> 5, lane = tid & 31;
    const int wm = wid & 3;          // m quadrant (32 rows)
    const int wn = wid >> 2;         // n half (32 cols)
    const int g  = lane >> 2;        // 0..7
    const int t  = lane & 3;         // 0..3
    const int m0 = blockIdx.y * 128;
    const int n0 = blockIdx.x * 64;

    float c[2][4][4];
    #pragma unroll
    for (int mf=0; mf<2; ++mf)
        #pragma unroll
        for (int nf=0; nf<4; ++nf)
            #pragma unroll
            for (int q=0; q<4; ++q) c[mf][nf][q] = 0.f;

    for (int kc = 0; kc < 16; ++kc){
        const int k0 = kc * 32;
        __syncthreads();
        // A tile: 128 rows x 32 = 1024 float4, 4 per thread
        #pragma unroll
        for (int it=0; it<4; ++it){
            int idx = tid + it*256;
            int row = idx >> 3, c4 = (idx & 7)*4;
            float4 v = *(const float4*)(A + (long)(m0+row)*D_ + k0 + c4);
            *(float4*)(sA + row*SA_STRIDE + c4) = v;
        }
        // W tile: 64 rows x 32 = 512 float4, 2 per thread
        #pragma unroll
        for (int it=0; it<2; ++it){
            int idx = tid + it*256;
            int row = idx >> 3, c4 = (idx & 7)*4;
            float4 v = *(const float4*)(W + (long)(n0+row)*D_ + k0 + c4);
            *(float4*)(sW + row*SA_STRIDE + c4) = v;
        }
        __syncthreads();

        #pragma unroll
        for (int ks=0; ks<4; ++ks){
            const int kb = ks*8;
            // A fragments (2 m-frags), split hi/lo
            uint32_t ahi[2][4], alo[2][4];
            #pragma unroll
            for (int mf=0; mf<2; ++mf){
                const int ra = wm*32 + mf*16;
                float x0 = sA[(ra+g  )*SA_STRIDE + kb+t  ];
                float x1 = sA[(ra+8+g)*SA_STRIDE + kb+t  ];
                float x2 = sA[(ra+g  )*SA_STRIDE + kb+t+4];
                float x3 = sA[(ra+8+g)*SA_STRIDE + kb+t+4];
                float h0=tf32_rd(x0), h1=tf32_rd(x1), h2=tf32_rd(x2), h3=tf32_rd(x3);
                ahi[mf][0]=__float_as_uint(h0); alo[mf][0]=__float_as_uint(tf32_rd(x0-h0));
                ahi[mf][1]=__float_as_uint(h1); alo[mf][1]=__float_as_uint(tf32_rd(x1-h1));
                ahi[mf][2]=__float_as_uint(h2); alo[mf][2]=__float_as_uint(tf32_rd(x2-h2));
                ahi[mf][3]=__float_as_uint(h3); alo[mf][3]=__float_as_uint(tf32_rd(x3-h3));
            }
            // B fragments (4 n-frags), split hi/lo
            uint32_t whi[4][2], wlo[4][2];
            #pragma unroll
            for (int nf=0; nf<4; ++nf){
                const int cn = wn*32 + nf*8 + g;
                float y0 = sW[cn*SA_STRIDE + kb+t  ];
                float y1 = sW[cn*SA_STRIDE + kb+t+4];
                float h0=tf32_rd(y0), h1=tf32_rd(y1);
                whi[nf][0]=__float_as_uint(h0); wlo[nf][0]=__float_as_uint(tf32_rd(y0-h0));
                whi[nf][1]=__float_as_uint(h1); wlo[nf][1]=__float_as_uint(tf32_rd(y1-h1));
            }
            #pragma unroll
            for (int mf=0; mf<2; ++mf)
                #pragma unroll
                for (int nf=0; nf<4; ++nf){
                    mma_tf32(c[mf][nf], ahi[mf], whi[nf]);
                    mma_tf32(c[mf][nf], ahi[mf], wlo[nf]);
                    mma_tf32(c[mf][nf], alo[mf], whi[nf]);
                }
        }
    }

    // epilogue
    #pragma unroll
    for (int mf=0; mf<2; ++mf){
        const int row0 = m0 + wm*32 + mf*16 + g;
        #pragma unroll
        for (int nf=0; nf<4; ++nf){
            const int ncol = n0 + wn*32 + nf*8 + 2*t;
            float2 bi = *(const float2*)(bias + ncol);
            float2 v0; v0.x = c[mf][nf][0] + bi.x; v0.y = c[mf][nf][1] + bi.y;
            float2 v1; v1.x = c[mf][nf][2] + bi.x; v1.y = c[mf][nf][3] + bi.y;
            if (head_split){
                int hh = ncol >> 6, dd = ncol & 63;
                int bb0 = row0 >> 10, ss0 = row0 & 1023;
                int bb1 = (row0+8) >> 10, ss1 = (row0+8) & 1023;
                *(float2*)(dst + (((long)bb0*H_ + hh)*S_ + ss0)*DK_ + dd) = v0;
                *(float2*)(dst + (((long)bb1*H_ + hh)*S_ + ss1)*DK_ + dd) = v1;
            } else {
                *(float2*)(dst + (long)row0*D_ + ncol) = v0;
                *(float2*)(dst + (long)(row0+8)*D_ + ncol) = v1;
            }
        }
    }
}

// ---------------------------------------------------------------------------
// Attention with distance decay (R5-proven config).
// ---------------------------------------------------------------------------
__global__ __launch_bounds__(512) void attn_kernel(
    const float* __restrict__ utT, const float* __restrict__ gammas)
{
    extern __shared__ float smem[];
    float* sS   = smem;
    float* sQ   = sS  + TM*SS_STRIDE;
    float* sKV  = sQ  + TM*SQ_STRIDE;
    float* sInv = sKV + KVBUF;

    const int i0 = blockIdx.x * TM;
    const int h  = blockIdx.y;
    const int b  = blockIdx.z;
    const int tid = threadIdx.x;
    const long bh = (long)(b*H_ + h);
    const float* Kbase = g_qk + bh*(long)(S_*DK_);
    const float* Vbase = g_v  + bh*(long)(S_*DK_);
    const int TJn  = (i0 + TM + BJ - 1) / BJ;
    const int JMAX = TJn * BJ;

    {
        int row = tid >> 4, c4 = (tid & 15)*4;
        float4 v = *(const float4*)(Kbase + (long)(i0+row)*DK_ + c4);
        *(float4*)(sQ + row*SQ_STRIDE + c4) = v;
    }

    const int tx = tid & 63;
    const int ty = tid >> 6;
    const float kscale = 0.125f;

    for (int jt=0; jt<TJn; ++jt){
        const int j0 = jt*BJ;
        __syncthreads();
        #pragma unroll
        for (int it=0; it<8; ++it){
            int idx = tid + it*512;
            int jrow = idx >> 4;
            int c4   = (idx & 15)*4;
            float4 v = *(const float4*)(Kbase + (long)(j0+jrow)*DK_ + c4);
            int js = jrow ^ c4;
            sKV[(c4+0)*SKT_STRIDE + js] = v.x;
            sKV[(c4+1)*SKT_STRIDE + js] = v.y;
            sKV[(c4+2)*SKT_STRIDE + js] = v.z;
            sKV[(c4+3)*SKT_STRIDE + js] = v.w;
        }
        __syncthreads();

        float acc[4][4] = {};
        #pragma unroll
        for (int kkc=0; kkc<16; ++kkc){
            const int cb = (tx*4) ^ (kkc*4);
            const float* kb = sKV + (kkc*4)*SKT_STRIDE + cb;
            float4 k0 = *(const float4*)(kb);
            float4 k1 = *(const float4*)(kb + SKT_STRIDE);
            float4 k2 = *(const float4*)(kb + 2*SKT_STRIDE);
            float4 k3 = *(const float4*)(kb + 3*SKT_STRIDE);
            #pragma unroll
            for (int r=0; r<4; ++r){
                float4 q = *(const float4*)(sQ + (ty*4+r)*SQ_STRIDE + kkc*4);
                acc[r][0] += q.x*k0.x + q.y*k1.x + q.z*k2.x + q.w*k3.x;
                acc[r][1] += q.x*k0.y + q.y*k1.y + q.z*k2.y + q.w*k3.y;
                acc[r][2] += q.x*k0.z + q.y*k1.z + q.z*k2.z + q.w*k3.z;
                acc[r][3] += q.x*k0.w + q.y*k1.w + q.z*k2.w + q.w*k3.w;
            }
        }

        const int jl = j0 + tx*4;
        #pragma unroll
        for (int r=0; r<4; ++r){
            int gi = i0 + ty*4 + r;
            float4 u4 = *(const float4*)(utT + ((long)b*S_ + gi)*S_ + jl);
            float4 w;
            w.x = acc[r][0]*kscale*u4.x;
            w.y = acc[r][1]*kscale*u4.y;
            w.z = acc[r][2]*kscale*u4.z;
            w.w = acc[r][3]*kscale*u4.w;
            *(float4*)(sS + (ty*4+r)*SS_STRIDE + jl) = w;
        }
    }
    __syncthreads();

    {
        const int wid = tid >> 5, lane = tid & 31;
        const unsigned FULL = 0xffffffffu;
        const float gh = -log1pf(__expf(gammas[h]));

        #pragma unroll 1
        for (int q=0; q<2; ++q){
            int r  = wid*2 + q;
            int gi = i0 + r;
            int L  = gi + 1;
            float* row = sS + r*SS_STRIDE;

            for (int j = L + lane; j < JMAX; j += 32) row[j] = 0.f;

            float mx = -1e30f;
            for (int j = lane; j < L; j += 32) mx = fmaxf(mx, row[j]);
            #pragma unroll
            for (int o=16;o>0;o>>=1) mx = fmaxf(mx, __shfl_xor_sync(FULL, mx, o));

            float sm = 0.f;
            for (int j = lane; j < L; j += 32) sm += __expf(row[j] - mx);
            #pragma unroll
            for (int o=16;o>0;o>>=1) sm += __shfl_xor_sync(FULL, sm, o);
            const float inv = 1.f / sm;

            float carry = 0.f, mx2 = -1e30f;
            int nch = (L + 31) >> 5;
            for (int c = 0; c < nch; ++c){
                int j = c*32 + lane;
                bool in = j < L;
                float s = in ? row[j] : 0.f;
                float e = in ? __expf(s - mx) : 0.f;
                float v = e;
                #pragma unroll
                for (int o=1;o<32;o<<=1){
                    float t = __shfl_up_sync(FULL, v, o);
                    if (lane >= o) v += t;
                }
                float cum = carry + v;
                carry += __shfl_sync(FULL, v, 31);
                if (in){
                    float rem = fmaxf(0.f, (sm - cum) * inv);
                    float pe  = fabsf((float)(gi - j));
                    float y   = rem * pe;
                    float dist = (y > 0.f) ? y * __frsqrt_rn(y) : 0.f;
                    float te = fmaxf(__expf(dist * gh), 1e-5f);
                    float s2 = s * te;
                    row[j] = s2;
                    mx2 = fmaxf(mx2, s2);
                }
            }
            #pragma unroll
            for (int o=16;o>0;o>>=1) mx2 = fmaxf(mx2, __shfl_xor_sync(FULL, mx2, o));

            float sm2 = 0.f;
            for (int j = lane; j < L; j += 32){
                float e2 = __expf(row[j] - mx2);
                row[j] = e2;
                sm2 += e2;
            }
            #pragma unroll
            for (int o=16;o>0;o>>=1) sm2 += __shfl_xor_sync(FULL, sm2, o);
            if (lane == 0) sInv[r] = 1.f / sm2;
        }
    }

    {
        const int rg = tid >> 4;
        const int dg = tid & 15;
        float a0=0.f, a1=0.f, a2=0.f, a3=0.f;

        for (int jt=0; jt<TJn; ++jt){
            const int j0 = jt*BJ;
            __syncthreads();
            #pragma unroll
            for (int it=0; it<8; ++it){
                int idx = tid + it*512;
                int row = idx >> 4, c4 = (idx & 15)*4;
                float4 v = *(const float4*)(Vbase + (long)(j0+row)*DK_ + c4);
                *(float4*)(sKV + row*SV_STRIDE + c4) = v;
            }
            __syncthreads();
            const float* prow = sS + rg*SS_STRIDE + j0;
            #pragma unroll 2
            for (int jj=0; jj<BJ; jj+=4){
                float4 p4 = *(const float4*)(prow + jj);
                const float* vb = sKV + jj*SV_STRIDE + dg*4;
                float4 v0 = *(const float4*)(vb);
                float4 v1 = *(const float4*)(vb + SV_STRIDE);
                float4 v2 = *(const float4*)(vb + 2*SV_STRIDE);
                float4 v3 = *(const float4*)(vb + 3*SV_STRIDE);
                a0 += p4.x*v0.x + p4.y*v1.x + p4.z*v2.x + p4.w*v3.x;
                a1 += p4.x*v0.y + p4.y*v1.y + p4.z*v2.y + p4.w*v3.y;
                a2 += p4.x*v0.z + p4.y*v1.z + p4.z*v2.z + p4.w*v3.z;
                a3 += p4.x*v0.w + p4.y*v1.w + p4.z*v2.w + p4.w*v3.w;
            }
        }

        float sc = sInv[rg];
        float4 w; w.x=a0*sc; w.y=a1*sc; w.z=a2*sc; w.w=a3*sc;
        *(float4*)(g_attn + ((long)b*S_ + i0 + rg)*D_ + h*DK_ + dg*4) = w;
    }
}

// ---------------------------------------------------------------------------
extern "C" void kernel_launch(void* const* d_in, const int* in_sizes, int n_in,
                              void* d_out, int out_size)
{
    const float* x      = (const float*)d_in[0];
    const float* utT    = (const float*)d_in[1];
    const float* Wk     = (const float*)d_in[2];
    const float* bk     = (const float*)d_in[3];
    const float* Wv     = (const float*)d_in[4];
    const float* bv     = (const float*)d_in[5];
    const float* Wo     = (const float*)d_in[6];
    const float* bo     = (const float*)d_in[7];
    const float* gammas = (const float*)d_in[8];
    float* out = (float*)d_out;

    float* qk; cudaGetSymbolAddress((void**)&qk, g_qk);
    float* vv; cudaGetSymbolAddress((void**)&vv, g_v);
    float* at; cudaGetSymbolAddress((void**)&at, g_attn);

    dim3 tg(D_/64, (B_*S_)/128);   // 8 x 64

    // QK + V projections on tensor cores (3xTF32)
    gemm_mma<<<tg, 256>>>(x, Wk, bk, qk, 1);
    gemm_mma<<<tg, 256>>>(x, Wv, bv, vv, 1);

    // attention
    size_t smem_bytes = (size_t)(TM*SS_STRIDE + TM*SQ_STRIDE + KVBUF + 32) * sizeof(float);
    cudaFuncSetAttribute(attn_kernel, cudaFuncAttributeMaxDynamicSharedMemorySize, (int)smem_bytes);
    attn_kernel<<<dim3(S_/TM, H_, B_), 512, smem_bytes>>>(utT, gammas);

    // output projection on tensor cores
    gemm_mma<<<tg, 256>>>(at, Wo, bo, out, 0);
}

// round 14
// speedup vs baseline: 1.3009x; 1.1805x over previous
#include <cuda_runtime.h>
#include <math.h>
#include <stdint.h>

#define B_ 8
#define S_ 1024
#define D_ 512
#define H_ 8
#define DK_ 64

#define TM 32
#define BJ 256
#define SS_STRIDE 1032
#define SQ_STRIDE 68
#define SV_STRIDE 68
#define KVBUF (BJ*SV_STRIDE)

// scratch (device globals; no allocation allowed)
__device__ float g_qk[B_*H_*S_*DK_];   // 16 MB, q == k (kq_same)
__device__ float g_v [B_*H_*S_*DK_];   // 16 MB
__device__ float g_attn[B_*S_*D_];     // 16 MB

// ---------------------------------------------------------------------------
// helpers
// ---------------------------------------------------------------------------
__device__ __forceinline__ float tf32_rd(float a){
    uint32_t u; asm("cvt.rna.tf32.f32 %0, %1;" : "=r"(u) : "f"(a));
    return __uint_as_float(u);
}
__device__ __forceinline__ void mma_tf32(float* c, const uint32_t* a, const uint32_t* b){
    asm volatile("mma.sync.aligned.m16n8k8.row.col.f32.tf32.tf32.f32 "
        "{%0,%1,%2,%3}, {%4,%5,%6,%7}, {%8,%9}, {%0,%1,%2,%3};"
        : "+f"(c[0]), "+f"(c[1]), "+f"(c[2]), "+f"(c[3])
        : "r"(a[0]), "r"(a[1]), "r"(a[2]), "r"(a[3]), "r"(b[0]), "r"(b[1]));
}
// split 4 floats into tf32 hi/lo fragment pairs
__device__ __forceinline__ void split4(const float* x, uint32_t* hi, uint32_t* lo){
    #pragma unroll
    for (int i=0;i<4;++i){
        float h = tf32_rd(x[i]);
        hi[i] = __float_as_uint(h);
        lo[i] = __float_as_uint(tf32_rd(x[i]-h));
    }
}
__device__ __forceinline__ void split2(const float* x, uint32_t* hi, uint32_t* lo){
    #pragma unroll
    for (int i=0;i<2;++i){
        float h = tf32_rd(x[i]);
        hi[i] = __float_as_uint(h);
        lo[i] = __float_as_uint(tf32_rd(x[i]-h));
    }
}

// ---------------------------------------------------------------------------
// Tensor-core 3xTF32 GEMM:  dst[M,N] = A[M,512] @ W[N,512]^T + bias
// Block tile 128x64, 8 warps (4m x 2n), K-chunks of 32, split in registers.
// ---------------------------------------------------------------------------
#define SA_STRIDE 36
__global__ __launch_bounds__(256) void gemm_mma(
    const float* __restrict__ A, const float* __restrict__ W,
    const float* __restrict__ bias, float* __restrict__ dst, int head_split)
{
    __shared__ float sA[128*SA_STRIDE];
    __shared__ float sW[64*SA_STRIDE];

    const int tid = threadIdx.x;
    const int wid = tid >> 5, lane = tid & 31;
    const int wm = wid & 3;
    const int wn = wid >> 2;
    const int g  = lane >> 2;
    const int t  = lane & 3;
    const int m0 = blockIdx.y * 128;
    const int n0 = blockIdx.x * 64;

    float c[2][4][4];
    #pragma unroll
    for (int mf=0; mf<2; ++mf)
        #pragma unroll
        for (int nf=0; nf<4; ++nf)
            #pragma unroll
            for (int q=0; q<4; ++q) c[mf][nf][q] = 0.f;

    for (int kc = 0; kc < 16; ++kc){
        const int k0 = kc * 32;
        __syncthreads();
        #pragma unroll
        for (int it=0; it<4; ++it){
            int idx = tid + it*256;
            int row = idx >> 3, c4 = (idx & 7)*4;
            float4 v = *(const float4*)(A + (long)(m0+row)*D_ + k0 + c4);
            *(float4*)(sA + row*SA_STRIDE + c4) = v;
        }
        #pragma unroll
        for (int it=0; it<2; ++it){
            int idx = tid + it*256;
            int row = idx >> 3, c4 = (idx & 7)*4;
            float4 v = *(const float4*)(W + (long)(n0+row)*D_ + k0 + c4);
            *(float4*)(sW + row*SA_STRIDE + c4) = v;
        }
        __syncthreads();

        #pragma unroll
        for (int ks=0; ks<4; ++ks){
            const int kb = ks*8;
            uint32_t ahi[2][4], alo[2][4];
            #pragma unroll
            for (int mf=0; mf<2; ++mf){
                const int ra = wm*32 + mf*16;
                float x[4];
                x[0] = sA[(ra+g  )*SA_STRIDE + kb+t  ];
                x[1] = sA[(ra+8+g)*SA_STRIDE + kb+t  ];
                x[2] = sA[(ra+g  )*SA_STRIDE + kb+t+4];
                x[3] = sA[(ra+8+g)*SA_STRIDE + kb+t+4];
                split4(x, ahi[mf], alo[mf]);
            }
            uint32_t whi[4][2], wlo[4][2];
            #pragma unroll
            for (int nf=0; nf<4; ++nf){
                const int cn = wn*32 + nf*8 + g;
                float y[2];
                y[0] = sW[cn*SA_STRIDE + kb+t  ];
                y[1] = sW[cn*SA_STRIDE + kb+t+4];
                split2(y, whi[nf], wlo[nf]);
            }
            #pragma unroll
            for (int mf=0; mf<2; ++mf)
                #pragma unroll
                for (int nf=0; nf<4; ++nf){
                    mma_tf32(c[mf][nf], ahi[mf], whi[nf]);
                    mma_tf32(c[mf][nf], ahi[mf], wlo[nf]);
                    mma_tf32(c[mf][nf], alo[mf], whi[nf]);
                }
        }
    }

    #pragma unroll
    for (int mf=0; mf<2; ++mf){
        const int row0 = m0 + wm*32 + mf*16 + g;
        #pragma unroll
        for (int nf=0; nf<4; ++nf){
            const int ncol = n0 + wn*32 + nf*8 + 2*t;
            float2 bi = *(const float2*)(bias + ncol);
            float2 v0; v0.x = c[mf][nf][0] + bi.x; v0.y = c[mf][nf][1] + bi.y;
            float2 v1; v1.x = c[mf][nf][2] + bi.x; v1.y = c[mf][nf][3] + bi.y;
            if (head_split){
                int hh = ncol >> 6, dd = ncol & 63;
                int bb0 = row0 >> 10, ss0 = row0 & 1023;
                int bb1 = (row0+8) >> 10, ss1 = (row0+8) & 1023;
                *(float2*)(dst + (((long)bb0*H_ + hh)*S_ + ss0)*DK_ + dd) = v0;
                *(float2*)(dst + (((long)bb1*H_ + hh)*S_ + ss1)*DK_ + dd) = v1;
            } else {
                *(float2*)(dst + (long)row0*D_ + ncol) = v0;
                *(float2*)(dst + (long)(row0+8)*D_ + ncol) = v1;
            }
        }
    }
}

// ---------------------------------------------------------------------------
// Attention with distance decay.  One block = 32 query rows of one (b,h),
// 512 threads.  Score + out GEMMs on mma.sync (3xTF32); softmax from R5.
// ---------------------------------------------------------------------------
__global__ __launch_bounds__(512) void attn_kernel(
    const float* __restrict__ utT, const float* __restrict__ gammas)
{
    extern __shared__ float smem[];
    float* sS   = smem;                    // 32 x 1032
    float* sQ   = sS  + TM*SS_STRIDE;      // 32 x 68
    float* sKV  = sQ  + TM*SQ_STRIDE;      // 256 x 68 (K or V, row-major)
    float* sInv = sKV + KVBUF;             // 32

    const int i0 = blockIdx.x * TM;
    const int h  = blockIdx.y;
    const int b  = blockIdx.z;
    const int tid = threadIdx.x;
    const int wid = tid >> 5, lane = tid & 31;
    const int g = lane >> 2, t = lane & 3;
    const long bh = (long)(b*H_ + h);
    const float* Kbase = g_qk + bh*(long)(S_*DK_);
    const float* Vbase = g_v  + bh*(long)(S_*DK_);
    const int TJn  = (i0 + TM + BJ - 1) / BJ;
    const int JMAX = TJn * BJ;
    const float kscale = 0.125f;

    // ---- load Q tile (32 x 64) ----
    {
        int row = tid >> 4, c4 = (tid & 15)*4;
        float4 v = *(const float4*)(Kbase + (long)(i0+row)*DK_ + c4);
        *(float4*)(sQ + row*SQ_STRIDE + c4) = v;
    }

    // ---- score GEMM (tensor): sS[i][j] = (q_i . k_j)/8 * utT[b,i,j] ----
    // 16 warps: warp w covers cols w*16 .. w*16+15 of the 256-tile.
    for (int jt=0; jt<TJn; ++jt){
        const int j0 = jt*BJ;
        __syncthreads();
        #pragma unroll
        for (int it=0; it<8; ++it){
            int idx = tid + it*512;
            int row = idx >> 4, c4 = (idx & 15)*4;
            float4 v = *(const float4*)(Kbase + (long)(j0+row)*DK_ + c4);
            *(float4*)(sKV + row*SV_STRIDE + c4) = v;
        }
        __syncthreads();

        float c[2][2][4];
        #pragma unroll
        for (int mf=0;mf<2;++mf)
            #pragma unroll
            for (int nf=0;nf<2;++nf)
                #pragma unroll
                for (int q=0;q<4;++q) c[mf][nf][q]=0.f;

        #pragma unroll
        for (int ks=0; ks<8; ++ks){
            const int kb = ks*8;
            uint32_t ahi[2][4], alo[2][4];
            #pragma unroll
            for (int mf=0; mf<2; ++mf){
                const int ra = mf*16;
                float x[4];
                x[0] = sQ[(ra+g  )*SQ_STRIDE + kb+t  ];
                x[1] = sQ[(ra+8+g)*SQ_STRIDE + kb+t  ];
                x[2] = sQ[(ra+g  )*SQ_STRIDE + kb+t+4];
                x[3] = sQ[(ra+8+g)*SQ_STRIDE + kb+t+4];
                split4(x, ahi[mf], alo[mf]);
            }
            uint32_t bhi[2][2], blo[2][2];
            #pragma unroll
            for (int nf=0; nf<2; ++nf){
                const int cn = wid*16 + nf*8 + g;     // key index in tile
                float y[2];
                y[0] = sKV[cn*SV_STRIDE + kb+t  ];
                y[1] = sKV[cn*SV_STRIDE + kb+t+4];
                split2(y, bhi[nf], blo[nf]);
            }
            #pragma unroll
            for (int mf=0; mf<2; ++mf)
                #pragma unroll
                for (int nf=0; nf<2; ++nf){
                    mma_tf32(c[mf][nf], ahi[mf], bhi[nf]);
                    mma_tf32(c[mf][nf], ahi[mf], blo[nf]);
                    mma_tf32(c[mf][nf], alo[mf], bhi[nf]);
                }
        }

        // epilogue: * kscale * utT, write to sS
        #pragma unroll
        for (int mf=0; mf<2; ++mf){
            const int r0 = mf*16 + g;
            #pragma unroll
            for (int nf=0; nf<2; ++nf){
                const int jl = j0 + wid*16 + nf*8 + 2*t;
                const int gi0 = i0 + r0, gi1 = gi0 + 8;
                float2 u0 = *(const float2*)(utT + ((long)b*S_ + gi0)*S_ + jl);
                float2 u1 = *(const float2*)(utT + ((long)b*S_ + gi1)*S_ + jl);
                float2 w0; w0.x = c[mf][nf][0]*kscale*u0.x; w0.y = c[mf][nf][1]*kscale*u0.y;
                float2 w1; w1.x = c[mf][nf][2]*kscale*u1.x; w1.y = c[mf][nf][3]*kscale*u1.y;
                *(float2*)(sS + r0*SS_STRIDE + jl) = w0;
                *(float2*)(sS + (r0+8)*SS_STRIDE + jl) = w1;
            }
        }
    }
    __syncthreads();

    // ---- per-row softmax1 -> cumsum -> decay -> exp2 (R5-proven) ----
    {
        const unsigned FULL = 0xffffffffu;
        const float gh = -log1pf(__expf(gammas[h]));

        #pragma unroll 1
        for (int q=0; q<2; ++q){
            int r  = wid*2 + q;
            int gi = i0 + r;
            int L  = gi + 1;
            float* row = sS + r*SS_STRIDE;

            for (int j = L + lane; j < JMAX; j += 32) row[j] = 0.f;

            float mx = -1e30f;
            for (int j = lane; j < L; j += 32) mx = fmaxf(mx, row[j]);
            #pragma unroll
            for (int o=16;o>0;o>>=1) mx = fmaxf(mx, __shfl_xor_sync(FULL, mx, o));

            float sm = 0.f;
            for (int j = lane; j < L; j += 32) sm += __expf(row[j] - mx);
            #pragma unroll
            for (int o=16;o>0;o>>=1) sm += __shfl_xor_sync(FULL, sm, o);
            const float inv = 1.f / sm;

            float carry = 0.f, mx2 = -1e30f;
            int nch = (L + 31) >> 5;
            for (int c = 0; c < nch; ++c){
                int j = c*32 + lane;
                bool in = j < L;
                float s = in ? row[j] : 0.f;
                float e = in ? __expf(s - mx) : 0.f;
                float v = e;
                #pragma unroll
                for (int o=1;o<32;o<<=1){
                    float tt = __shfl_up_sync(FULL, v, o);
                    if (lane >= o) v += tt;
                }
                float cum = carry + v;
                carry += __shfl_sync(FULL, v, 31);
                if (in){
                    float rem = fmaxf(0.f, (sm - cum) * inv);
                    float pe  = fabsf((float)(gi - j));
                    float y   = rem * pe;
                    float dist = (y > 0.f) ? y * __frsqrt_rn(y) : 0.f;
                    float te = fmaxf(__expf(dist * gh), 1e-5f);
                    float s2 = s * te;
                    row[j] = s2;
                    mx2 = fmaxf(mx2, s2);
                }
            }
            #pragma unroll
            for (int o=16;o>0;o>>=1) mx2 = fmaxf(mx2, __shfl_xor_sync(FULL, mx2, o));

            float sm2 = 0.f;
            for (int j = lane; j < L; j += 32){
                float e2 = __expf(row[j] - mx2);
                row[j] = e2;
                sm2 += e2;
            }
            #pragma unroll
            for (int o=16;o>0;o>>=1) sm2 += __shfl_xor_sync(FULL, sm2, o);
            if (lane == 0) sInv[r] = 1.f / sm2;
        }
    }

    // ---- out GEMM (tensor): out[i][d] = sInv[i] * sum_j e2[i][j]*v[j][d] --
    // 16 warps: wm = wid>>3 (16-row half), wn = wid&7 (8-col slice of 64).
    {
        const int wm = wid >> 3;
        const int wn = wid & 7;
        float c[4] = {0.f, 0.f, 0.f, 0.f};

        for (int jt=0; jt<TJn; ++jt){
            const int j0 = jt*BJ;
            __syncthreads();
            #pragma unroll
            for (int it=0; it<8; ++it){
                int idx = tid + it*512;
                int row = idx >> 4, c4 = (idx & 15)*4;
                float4 v = *(const float4*)(Vbase + (long)(j0+row)*DK_ + c4);
                *(float4*)(sKV + row*SV_STRIDE + c4) = v;
            }
            __syncthreads();

            #pragma unroll 4
            for (int ks=0; ks<32; ++ks){
                const int kb = ks*8;
                float x[4];
                x[0] = sS[(wm*16+g  )*SS_STRIDE + j0+kb+t  ];
                x[1] = sS[(wm*16+8+g)*SS_STRIDE + j0+kb+t  ];
                x[2] = sS[(wm*16+g  )*SS_STRIDE + j0+kb+t+4];
                x[3] = sS[(wm*16+8+g)*SS_STRIDE + j0+kb+t+4];
                uint32_t ahi[4], alo[4];
                split4(x, ahi, alo);
                float y[2];
                y[0] = sKV[(kb+t  )*SV_STRIDE + wn*8+g];
                y[1] = sKV[(kb+t+4)*SV_STRIDE + wn*8+g];
                uint32_t bhi[2], blo[2];
                split2(y, bhi, blo);
                mma_tf32(c, ahi, bhi);
                mma_tf32(c, ahi, blo);
                mma_tf32(c, alo, bhi);
            }
        }

        const int r0 = wm*16 + g;
        const int col = h*DK_ + wn*8 + 2*t;
        float sc0 = sInv[r0], sc1 = sInv[r0+8];
        float2 w0; w0.x = c[0]*sc0; w0.y = c[1]*sc0;
        float2 w1; w1.x = c[2]*sc1; w1.y = c[3]*sc1;
        *(float2*)(g_attn + ((long)b*S_ + i0 + r0)*D_ + col) = w0;
        *(float2*)(g_attn + ((long)b*S_ + i0 + r0 + 8)*D_ + col) = w1;
    }
}

// ---------------------------------------------------------------------------
extern "C" void kernel_launch(void* const* d_in, const int* in_sizes, int n_in,
                              void* d_out, int out_size)
{
    const float* x      = (const float*)d_in[0];
    const float* utT    = (const float*)d_in[1];
    const float* Wk     = (const float*)d_in[2];
    const float* bk     = (const float*)d_in[3];
    const float* Wv     = (const float*)d_in[4];
    const float* bv     = (const float*)d_in[5];
    const float* Wo     = (const float*)d_in[6];
    const float* bo     = (const float*)d_in[7];
    const float* gammas = (const float*)d_in[8];
    float* out = (float*)d_out;

    float* qk; cudaGetSymbolAddress((void**)&qk, g_qk);
    float* vv; cudaGetSymbolAddress((void**)&vv, g_v);
    float* at; cudaGetSymbolAddress((void**)&at, g_attn);

    dim3 tg(D_/64, (B_*S_)/128);   // 8 x 64

    // QK + V projections on tensor cores (3xTF32)
    gemm_mma<<<tg, 256>>>(x, Wk, bk, qk, 1);
    gemm_mma<<<tg, 256>>>(x, Wv, bv, vv, 1);

    // attention (tensor-core score/out GEMMs)
    size_t smem_bytes = (size_t)(TM*SS_STRIDE + TM*SQ_STRIDE + KVBUF + 32) * sizeof(float);
    cudaFuncSetAttribute(attn_kernel, cudaFuncAttributeMaxDynamicSharedMemorySize, (int)smem_bytes);
    attn_kernel<<<dim3(S_/TM, H_, B_), 512, smem_bytes>>>(utT, gammas);

    // output projection on tensor cores
    gemm_mma<<<tg, 256>>>(at, Wo, bo, out, 0);
}

// round 15
// speedup vs baseline: 1.3204x; 1.0150x over previous
#include <cuda_runtime.h>
#include <math.h>
#include <stdint.h>

#define B_ 8
#define S_ 1024
#define D_ 512
#define H_ 8
#define DK_ 64

#define TM 16
#define BJ 128
#define SS_STRIDE 1032
#define SQ_STRIDE 68
#define SV_STRIDE 68
#define KVBUF (BJ*SV_STRIDE)

// scratch (device globals; no allocation allowed)
__device__ float g_qk[B_*H_*S_*DK_];   // 16 MB, q == k (kq_same)
__device__ float g_v [B_*H_*S_*DK_];   // 16 MB
__device__ float g_attn[B_*S_*D_];     // 16 MB

// ---------------------------------------------------------------------------
// helpers
// ---------------------------------------------------------------------------
__device__ __forceinline__ float tf32_rd(float a){
    uint32_t u; asm("cvt.rna.tf32.f32 %0, %1;" : "=r"(u) : "f"(a));
    return __uint_as_float(u);
}
__device__ __forceinline__ void mma_tf32(float* c, const uint32_t* a, const uint32_t* b){
    asm volatile("mma.sync.aligned.m16n8k8.row.col.f32.tf32.tf32.f32 "
        "{%0,%1,%2,%3}, {%4,%5,%6,%7}, {%8,%9}, {%0,%1,%2,%3};"
        : "+f"(c[0]), "+f"(c[1]), "+f"(c[2]), "+f"(c[3])
        : "r"(a[0]), "r"(a[1]), "r"(a[2]), "r"(a[3]), "r"(b[0]), "r"(b[1]));
}
__device__ __forceinline__ void split4(const float* x, uint32_t* hi, uint32_t* lo){
    #pragma unroll
    for (int i=0;i<4;++i){
        float h = tf32_rd(x[i]);
        hi[i] = __float_as_uint(h);
        lo[i] = __float_as_uint(tf32_rd(x[i]-h));
    }
}
__device__ __forceinline__ void split2(const float* x, uint32_t* hi, uint32_t* lo){
    #pragma unroll
    for (int i=0;i<2;++i){
        float h = tf32_rd(x[i]);
        hi[i] = __float_as_uint(h);
        lo[i] = __float_as_uint(tf32_rd(x[i]-h));
    }
}

// ---------------------------------------------------------------------------
// Tensor-core 3xTF32 GEMM:  dst[M,N] = A[M,512] @ W[N,512]^T + bias
// (unchanged from R14; measured 98us, tensor=43%)
// ---------------------------------------------------------------------------
#define SA_STRIDE 36
__global__ __launch_bounds__(256) void gemm_mma(
    const float* __restrict__ A, const float* __restrict__ W,
    const float* __restrict__ bias, float* __restrict__ dst, int head_split)
{
    __shared__ float sA[128*SA_STRIDE];
    __shared__ float sW[64*SA_STRIDE];

    const int tid = threadIdx.x;
    const int wid = tid >> 5, lane = tid & 31;
    const int wm = wid & 3;
    const int wn = wid >> 2;
    const int g  = lane >> 2;
    const int t  = lane & 3;
    const int m0 = blockIdx.y * 128;
    const int n0 = blockIdx.x * 64;

    float c[2][4][4];
    #pragma unroll
    for (int mf=0; mf<2; ++mf)
        #pragma unroll
        for (int nf=0; nf<4; ++nf)
            #pragma unroll
            for (int q=0; q<4; ++q) c[mf][nf][q] = 0.f;

    for (int kc = 0; kc < 16; ++kc){
        const int k0 = kc * 32;
        __syncthreads();
        #pragma unroll
        for (int it=0; it<4; ++it){
            int idx = tid + it*256;
            int row = idx >> 3, c4 = (idx & 7)*4;
            float4 v = *(const float4*)(A + (long)(m0+row)*D_ + k0 + c4);
            *(float4*)(sA + row*SA_STRIDE + c4) = v;
        }
        #pragma unroll
        for (int it=0; it<2; ++it){
            int idx = tid + it*256;
            int row = idx >> 3, c4 = (idx & 7)*4;
            float4 v = *(const float4*)(W + (long)(n0+row)*D_ + k0 + c4);
            *(float4*)(sW + row*SA_STRIDE + c4) = v;
        }
        __syncthreads();

        #pragma unroll
        for (int ks=0; ks<4; ++ks){
            const int kb = ks*8;
            uint32_t ahi[2][4], alo[2][4];
            #pragma unroll
            for (int mf=0; mf<2; ++mf){
                const int ra = wm*32 + mf*16;
                float x[4];
                x[0] = sA[(ra+g  )*SA_STRIDE + kb+t  ];
                x[1] = sA[(ra+8+g)*SA_STRIDE + kb+t  ];
                x[2] = sA[(ra+g  )*SA_STRIDE + kb+t+4];
                x[3] = sA[(ra+8+g)*SA_STRIDE + kb+t+4];
                split4(x, ahi[mf], alo[mf]);
            }
            uint32_t whi[4][2], wlo[4][2];
            #pragma unroll
            for (int nf=0; nf<4; ++nf){
                const int cn = wn*32 + nf*8 + g;
                float y[2];
                y[0] = sW[cn*SA_STRIDE + kb+t  ];
                y[1] = sW[cn*SA_STRIDE + kb+t+4];
                split2(y, whi[nf], wlo[nf]);
            }
            #pragma unroll
            for (int mf=0; mf<2; ++mf)
                #pragma unroll
                for (int nf=0; nf<4; ++nf){
                    mma_tf32(c[mf][nf], ahi[mf], whi[nf]);
                    mma_tf32(c[mf][nf], ahi[mf], wlo[nf]);
                    mma_tf32(c[mf][nf], alo[mf], whi[nf]);
                }
        }
    }

    #pragma unroll
    for (int mf=0; mf<2; ++mf){
        const int row0 = m0 + wm*32 + mf*16 + g;
        #pragma unroll
        for (int nf=0; nf<4; ++nf){
            const int ncol = n0 + wn*32 + nf*8 + 2*t;
            float2 bi = *(const float2*)(bias + ncol);
            float2 v0; v0.x = c[mf][nf][0] + bi.x; v0.y = c[mf][nf][1] + bi.y;
            float2 v1; v1.x = c[mf][nf][2] + bi.x; v1.y = c[mf][nf][3] + bi.y;
            if (head_split){
                int hh = ncol >> 6, dd = ncol & 63;
                int bb0 = row0 >> 10, ss0 = row0 & 1023;
                int bb1 = (row0+8) >> 10, ss1 = (row0+8) & 1023;
                *(float2*)(dst + (((long)bb0*H_ + hh)*S_ + ss0)*DK_ + dd) = v0;
                *(float2*)(dst + (((long)bb1*H_ + hh)*S_ + ss1)*DK_ + dd) = v1;
            } else {
                *(float2*)(dst + (long)row0*D_ + ncol) = v0;
                *(float2*)(dst + (long)(row0+8)*D_ + ncol) = v1;
            }
        }
    }
}

// ---------------------------------------------------------------------------
// Attention with distance decay.  One block = 16 query rows of one (b,h),
// 256 threads, 2 blocks/SM (105KB smem).  Tensor-core score/out GEMMs.
// ---------------------------------------------------------------------------
__global__ __launch_bounds__(256, 2) void attn_kernel(
    const float* __restrict__ utT, const float* __restrict__ gammas)
{
    extern __shared__ float smem[];
    float* sS   = smem;                    // 16 x 1032
    float* sQ   = sS  + TM*SS_STRIDE;      // 16 x 68
    float* sKV  = sQ  + TM*SQ_STRIDE;      // 128 x 68 (K or V, row-major)
    float* sInv = sKV + KVBUF;             // 16

    const int i0 = blockIdx.x * TM;
    const int h  = blockIdx.y;
    const int b  = blockIdx.z;
    const int tid = threadIdx.x;
    const int wid = tid >> 5, lane = tid & 31;
    const int g = lane >> 2, t = lane & 3;
    const long bh = (long)(b*H_ + h);
    const float* Kbase = g_qk + bh*(long)(S_*DK_);
    const float* Vbase = g_v  + bh*(long)(S_*DK_);
    const int TJn  = (i0 + TM + BJ - 1) / BJ;
    const int JMAX = TJn * BJ;
    const float kscale = 0.125f;

    // ---- load Q tile (16 x 64): one float4 per thread ----
    {
        int row = tid >> 4, c4 = (tid & 15)*4;
        float4 v = *(const float4*)(Kbase + (long)(i0+row)*DK_ + c4);
        *(float4*)(sQ + row*SQ_STRIDE + c4) = v;
    }

    // ---- score GEMM (tensor): warp w covers cols w*16..+15 of 128-tile ----
    for (int jt=0; jt<TJn; ++jt){
        const int j0 = jt*BJ;
        __syncthreads();
        // K tile: 128 rows x 16 float4 = 2048 float4 / 256 thr = 8 each
        #pragma unroll
        for (int it=0; it<8; ++it){
            int idx = tid + it*256;
            int row = idx >> 4, c4 = (idx & 15)*4;
            float4 v = *(const float4*)(Kbase + (long)(j0+row)*DK_ + c4);
            *(float4*)(sKV + row*SV_STRIDE + c4) = v;
        }
        __syncthreads();

        float c[2][4];
        #pragma unroll
        for (int nf=0;nf<2;++nf)
            #pragma unroll
            for (int q=0;q<4;++q) c[nf][q]=0.f;

        #pragma unroll
        for (int ks=0; ks<8; ++ks){
            const int kb = ks*8;
            uint32_t ahi[4], alo[4];
            {
                float x[4];
                x[0] = sQ[(g  )*SQ_STRIDE + kb+t  ];
                x[1] = sQ[(8+g)*SQ_STRIDE + kb+t  ];
                x[2] = sQ[(g  )*SQ_STRIDE + kb+t+4];
                x[3] = sQ[(8+g)*SQ_STRIDE + kb+t+4];
                split4(x, ahi, alo);
            }
            uint32_t bhi[2][2], blo[2][2];
            #pragma unroll
            for (int nf=0; nf<2; ++nf){
                const int cn = wid*16 + nf*8 + g;
                float y[2];
                y[0] = sKV[cn*SV_STRIDE + kb+t  ];
                y[1] = sKV[cn*SV_STRIDE + kb+t+4];
                split2(y, bhi[nf], blo[nf]);
            }
            #pragma unroll
            for (int nf=0; nf<2; ++nf){
                mma_tf32(c[nf], ahi, bhi[nf]);
                mma_tf32(c[nf], ahi, blo[nf]);
                mma_tf32(c[nf], alo, bhi[nf]);
            }
        }

        // epilogue: * kscale * utT, write to sS
        #pragma unroll
        for (int nf=0; nf<2; ++nf){
            const int jl = j0 + wid*16 + nf*8 + 2*t;
            const int gi0 = i0 + g, gi1 = gi0 + 8;
            float2 u0 = *(const float2*)(utT + ((long)b*S_ + gi0)*S_ + jl);
            float2 u1 = *(const float2*)(utT + ((long)b*S_ + gi1)*S_ + jl);
            float2 w0; w0.x = c[nf][0]*kscale*u0.x; w0.y = c[nf][1]*kscale*u0.y;
            float2 w1; w1.x = c[nf][2]*kscale*u1.x; w1.y = c[nf][3]*kscale*u1.y;
            *(float2*)(sS + g*SS_STRIDE + jl) = w0;
            *(float2*)(sS + (8+g)*SS_STRIDE + jl) = w1;
        }
    }
    __syncthreads();

    // ---- per-row softmax1 -> cumsum -> decay -> exp2 (R5-proven) ----
    {
        const unsigned FULL = 0xffffffffu;
        const float gh = -log1pf(__expf(gammas[h]));

        #pragma unroll 1
        for (int q=0; q<2; ++q){
            int r  = wid*2 + q;
            int gi = i0 + r;
            int L  = gi + 1;
            float* row = sS + r*SS_STRIDE;

            for (int j = L + lane; j < JMAX; j += 32) row[j] = 0.f;

            float mx = -1e30f;
            for (int j = lane; j < L; j += 32) mx = fmaxf(mx, row[j]);
            #pragma unroll
            for (int o=16;o>0;o>>=1) mx = fmaxf(mx, __shfl_xor_sync(FULL, mx, o));

            float sm = 0.f;
            for (int j = lane; j < L; j += 32) sm += __expf(row[j] - mx);
            #pragma unroll
            for (int o=16;o>0;o>>=1) sm += __shfl_xor_sync(FULL, sm, o);
            const float inv = 1.f / sm;

            float carry = 0.f, mx2 = -1e30f;
            int nch = (L + 31) >> 5;
            for (int c = 0; c < nch; ++c){
                int j = c*32 + lane;
                bool in = j < L;
                float s = in ? row[j] : 0.f;
                float e = in ? __expf(s - mx) : 0.f;
                float v = e;
                #pragma unroll
                for (int o=1;o<32;o<<=1){
                    float tt = __shfl_up_sync(FULL, v, o);
                    if (lane >= o) v += tt;
                }
                float cum = carry + v;
                carry += __shfl_sync(FULL, v, 31);
                if (in){
                    float rem = fmaxf(0.f, (sm - cum) * inv);
                    float pe  = fabsf((float)(gi - j));
                    float y   = rem * pe;
                    float dist = (y > 0.f) ? y * __frsqrt_rn(y) : 0.f;
                    float te = fmaxf(__expf(dist * gh), 1e-5f);
                    float s2 = s * te;
                    row[j] = s2;
                    mx2 = fmaxf(mx2, s2);
                }
            }
            #pragma unroll
            for (int o=16;o>0;o>>=1) mx2 = fmaxf(mx2, __shfl_xor_sync(FULL, mx2, o));

            float sm2 = 0.f;
            for (int j = lane; j < L; j += 32){
                float e2 = __expf(row[j] - mx2);
                row[j] = e2;
                sm2 += e2;
            }
            #pragma unroll
            for (int o=16;o>0;o>>=1) sm2 += __shfl_xor_sync(FULL, sm2, o);
            if (lane == 0) sInv[r] = 1.f / sm2;
        }
    }

    // ---- out GEMM (tensor): 8 warps, warp w covers d-cols w*8..+7 ----
    {
        float c[4] = {0.f, 0.f, 0.f, 0.f};

        for (int jt=0; jt<TJn; ++jt){
            const int j0 = jt*BJ;
            __syncthreads();
            #pragma unroll
            for (int it=0; it<8; ++it){
                int idx = tid + it*256;
                int row = idx >> 4, c4 = (idx & 15)*4;
                float4 v = *(const float4*)(Vbase + (long)(j0+row)*DK_ + c4);
                *(float4*)(sKV + row*SV_STRIDE + c4) = v;
            }
            __syncthreads();

            #pragma unroll 4
            for (int ks=0; ks<16; ++ks){
                const int kb = ks*8;
                float x[4];
                x[0] = sS[(g  )*SS_STRIDE + j0+kb+t  ];
                x[1] = sS[(8+g)*SS_STRIDE + j0+kb+t  ];
                x[2] = sS[(g  )*SS_STRIDE + j0+kb+t+4];
                x[3] = sS[(8+g)*SS_STRIDE + j0+kb+t+4];
                uint32_t ahi[4], alo[4];
                split4(x, ahi, alo);
                float y[2];
                y[0] = sKV[(kb+t  )*SV_STRIDE + wid*8+g];
                y[1] = sKV[(kb+t+4)*SV_STRIDE + wid*8+g];
                uint32_t bhi[2], blo[2];
                split2(y, bhi, blo);
                mma_tf32(c, ahi, bhi);
                mma_tf32(c, ahi, blo);
                mma_tf32(c, alo, bhi);
            }
        }

        const int col = h*DK_ + wid*8 + 2*t;
        float sc0 = sInv[g], sc1 = sInv[g+8];
        float2 w0; w0.x = c[0]*sc0; w0.y = c[1]*sc0;
        float2 w1; w1.x = c[2]*sc1; w1.y = c[3]*sc1;
        *(float2*)(g_attn + ((long)b*S_ + i0 + g)*D_ + col) = w0;
        *(float2*)(g_attn + ((long)b*S_ + i0 + g + 8)*D_ + col) = w1;
    }
}

// ---------------------------------------------------------------------------
extern "C" void kernel_launch(void* const* d_in, const int* in_sizes, int n_in,
                              void* d_out, int out_size)
{
    const float* x      = (const float*)d_in[0];
    const float* utT    = (const float*)d_in[1];
    const float* Wk     = (const float*)d_in[2];
    const float* bk     = (const float*)d_in[3];
    const float* Wv     = (const float*)d_in[4];
    const float* bv     = (const float*)d_in[5];
    const float* Wo     = (const float*)d_in[6];
    const float* bo     = (const float*)d_in[7];
    const float* gammas = (const float*)d_in[8];
    float* out = (float*)d_out;

    float* qk; cudaGetSymbolAddress((void**)&qk, g_qk);
    float* vv; cudaGetSymbolAddress((void**)&vv, g_v);
    float* at; cudaGetSymbolAddress((void**)&at, g_attn);

    dim3 tg(D_/64, (B_*S_)/128);   // 8 x 64

    // QK + V projections on tensor cores (3xTF32)
    gemm_mma<<<tg, 256>>>(x, Wk, bk, qk, 1);
    gemm_mma<<<tg, 256>>>(x, Wv, bv, vv, 1);

    // attention (tensor-core score/out GEMMs, 2 blocks/SM)
    size_t smem_bytes = (size_t)(TM*SS_STRIDE + TM*SQ_STRIDE + KVBUF + TM) * sizeof(float);
    cudaFuncSetAttribute(attn_kernel, cudaFuncAttributeMaxDynamicSharedMemorySize, (int)smem_bytes);
    attn_kernel<<<dim3(S_/TM, H_, B_), 256, smem_bytes>>>(utT, gammas);

    // output projection on tensor cores
    gemm_mma<<<tg, 256>>>(at, Wo, bo, out, 0);
}

// round 17
// speedup vs baseline: 1.4115x; 1.0690x over previous
#include <cuda_runtime.h>
#include <math.h>
#include <stdint.h>

#define B_ 8
#define S_ 1024
#define D_ 512
#define H_ 8
#define DK_ 64

#define TM 16
#define BJ 128
#define SS_STRIDE 1032
#define SQ_STRIDE 68
#define SV_STRIDE 68
#define KVBUF (BJ*SV_STRIDE)

// scratch (device globals; no allocation allowed)
__device__ float g_qk[B_*H_*S_*DK_];     // 16 MB, q == k (kq_same)
__device__ float g_v [B_*H_*S_*DK_];     // 16 MB
__device__ float g_attn[B_*S_*D_];       // 16 MB
__device__ float g_p  [(long)B_*H_*S_*S_]; // 268 MB unnormalized probs (zero-padded to JZ)
__device__ float g_sinv[B_*H_*S_];       // 256 KB per-row 1/sum

// ---------------------------------------------------------------------------
// helpers
// ---------------------------------------------------------------------------
__device__ __forceinline__ float tf32_rd(float a){
    uint32_t u; asm("cvt.rna.tf32.f32 %0, %1;" : "=r"(u) : "f"(a));
    return __uint_as_float(u);
}
__device__ __forceinline__ void mma_tf32(float* c, const uint32_t* a, const uint32_t* b){
    asm volatile("mma.sync.aligned.m16n8k8.row.col.f32.tf32.tf32.f32 "
        "{%0,%1,%2,%3}, {%4,%5,%6,%7}, {%8,%9}, {%0,%1,%2,%3};"
        : "+f"(c[0]), "+f"(c[1]), "+f"(c[2]), "+f"(c[3])
        : "r"(a[0]), "r"(a[1]), "r"(a[2]), "r"(a[3]), "r"(b[0]), "r"(b[1]));
}
__device__ __forceinline__ void split4(const float* x, uint32_t* hi, uint32_t* lo){
    #pragma unroll
    for (int i=0;i<4;++i){
        float h = tf32_rd(x[i]);
        hi[i] = __float_as_uint(h);
        lo[i] = __float_as_uint(tf32_rd(x[i]-h));
    }
}
__device__ __forceinline__ void split2(const float* x, uint32_t* hi, uint32_t* lo){
    #pragma unroll
    for (int i=0;i<2;++i){
        float h = tf32_rd(x[i]);
        hi[i] = __float_as_uint(h);
        lo[i] = __float_as_uint(tf32_rd(x[i]-h));
    }
}

// ---------------------------------------------------------------------------
// Tensor-core 3xTF32 GEMM:  dst[M,N] = A[M,512] @ W[N,512]^T + bias
// (measured 98-99us, tensor=43%)
// ---------------------------------------------------------------------------
#define SA_STRIDE 36
__global__ __launch_bounds__(256) void gemm_mma(
    const float* __restrict__ A, const float* __restrict__ W,
    const float* __restrict__ bias, float* __restrict__ dst, int head_split)
{
    __shared__ float sA[128*SA_STRIDE];
    __shared__ float sW[64*SA_STRIDE];

    const int tid = threadIdx.x;
    const int wid = tid >> 5, lane = tid & 31;
    const int wm = wid & 3;
    const int wn = wid >> 2;
    const int g  = lane >> 2;
    const int t  = lane & 3;
    const int m0 = blockIdx.y * 128;
    const int n0 = blockIdx.x * 64;

    float c[2][4][4];
    #pragma unroll
    for (int mf=0; mf<2; ++mf)
        #pragma unroll
        for (int nf=0; nf<4; ++nf)
            #pragma unroll
            for (int q=0; q<4; ++q) c[mf][nf][q] = 0.f;

    for (int kc = 0; kc < 16; ++kc){
        const int k0 = kc * 32;
        __syncthreads();
        #pragma unroll
        for (int it=0; it<4; ++it){
            int idx = tid + it*256;
            int row = idx >> 3, c4 = (idx & 7)*4;
            float4 v = *(const float4*)(A + (long)(m0+row)*D_ + k0 + c4);
            *(float4*)(sA + row*SA_STRIDE + c4) = v;
        }
        #pragma unroll
        for (int it=0; it<2; ++it){
            int idx = tid + it*256;
            int row = idx >> 3, c4 = (idx & 7)*4;
            float4 v = *(const float4*)(W + (long)(n0+row)*D_ + k0 + c4);
            *(float4*)(sW + row*SA_STRIDE + c4) = v;
        }
        __syncthreads();

        #pragma unroll
        for (int ks=0; ks<4; ++ks){
            const int kb = ks*8;
            uint32_t ahi[2][4], alo[2][4];
            #pragma unroll
            for (int mf=0; mf<2; ++mf){
                const int ra = wm*32 + mf*16;
                float x[4];
                x[0] = sA[(ra+g  )*SA_STRIDE + kb+t  ];
                x[1] = sA[(ra+8+g)*SA_STRIDE + kb+t  ];
                x[2] = sA[(ra+g  )*SA_STRIDE + kb+t+4];
                x[3] = sA[(ra+8+g)*SA_STRIDE + kb+t+4];
                split4(x, ahi[mf], alo[mf]);
            }
            uint32_t whi[4][2], wlo[4][2];
            #pragma unroll
            for (int nf=0; nf<4; ++nf){
                const int cn = wn*32 + nf*8 + g;
                float y[2];
                y[0] = sW[cn*SA_STRIDE + kb+t  ];
                y[1] = sW[cn*SA_STRIDE + kb+t+4];
                split2(y, whi[nf], wlo[nf]);
            }
            #pragma unroll
            for (int mf=0; mf<2; ++mf)
                #pragma unroll
                for (int nf=0; nf<4; ++nf){
                    mma_tf32(c[mf][nf], ahi[mf], whi[nf]);
                    mma_tf32(c[mf][nf], ahi[mf], wlo[nf]);
                    mma_tf32(c[mf][nf], alo[mf], whi[nf]);
                }
        }
    }

    #pragma unroll
    for (int mf=0; mf<2; ++mf){
        const int row0 = m0 + wm*32 + mf*16 + g;
        #pragma unroll
        for (int nf=0; nf<4; ++nf){
            const int ncol = n0 + wn*32 + nf*8 + 2*t;
            float2 bi = *(const float2*)(bias + ncol);
            float2 v0; v0.x = c[mf][nf][0] + bi.x; v0.y = c[mf][nf][1] + bi.y;
            float2 v1; v1.x = c[mf][nf][2] + bi.x; v1.y = c[mf][nf][3] + bi.y;
            if (head_split){
                int hh = ncol >> 6, dd = ncol & 63;
                int bb0 = row0 >> 10, ss0 = row0 & 1023;
                int bb1 = (row0+8) >> 10, ss1 = (row0+8) & 1023;
                *(float2*)(dst + (((long)bb0*H_ + hh)*S_ + ss0)*DK_ + dd) = v0;
                *(float2*)(dst + (((long)bb1*H_ + hh)*S_ + ss1)*DK_ + dd) = v1;
            } else {
                *(float2*)(dst + (long)row0*D_ + ncol) = v0;
                *(float2*)(dst + (long)(row0+8)*D_ + ncol) = v1;
            }
        }
    }
}

// ---------------------------------------------------------------------------
// Kernel A: score GEMM (tensor) + softmax chain; writes unnormalized e2 to
// g_p (zero-padded to the 128-aligned causal boundary) and 1/sum to g_sinv.
// One block = 16 query rows of one (b,h), 256 threads, 2 blocks/SM.
// ---------------------------------------------------------------------------
__global__ __launch_bounds__(256, 2) void score_kernel(
    const float* __restrict__ utT, const float* __restrict__ gammas)
{
    extern __shared__ float smem[];
    float* sS   = smem;                    // 16 x 1032
    float* sQ   = sS  + TM*SS_STRIDE;      // 16 x 68
    float* sKV  = sQ  + TM*SQ_STRIDE;      // 128 x 68 (K, row-major)

    const int i0 = blockIdx.x * TM;
    const int h  = blockIdx.y;
    const int b  = blockIdx.z;
    const int tid = threadIdx.x;
    const int wid = tid >> 5, lane = tid & 31;
    const int g = lane >> 2, t = lane & 3;
    const long bh = (long)(b*H_ + h);
    const float* Kbase = g_qk + bh*(long)(S_*DK_);
    const int TJn = (i0 + TM + BJ - 1) / BJ;
    const int JZ  = ((i0 >> 7) + 1) << 7;   // 128-aligned causal boundary
    const float kscale = 0.125f;

    // ---- load Q tile (16 x 64) ----
    {
        int row = tid >> 4, c4 = (tid & 15)*4;
        float4 v = *(const float4*)(Kbase + (long)(i0+row)*DK_ + c4);
        *(float4*)(sQ + row*SQ_STRIDE + c4) = v;
    }

    // ---- score GEMM (tensor): warp w covers cols w*16..+15 of 128-tile ----
    for (int jt=0; jt<TJn; ++jt){
        const int j0 = jt*BJ;
        __syncthreads();
        #pragma unroll
        for (int it=0; it<8; ++it){
            int idx = tid + it*256;
            int row = idx >> 4, c4 = (idx & 15)*4;
            float4 v = *(const float4*)(Kbase + (long)(j0+row)*DK_ + c4);
            *(float4*)(sKV + row*SV_STRIDE + c4) = v;
        }
        __syncthreads();

        float c[2][4];
        #pragma unroll
        for (int nf=0;nf<2;++nf)
            #pragma unroll
            for (int q=0;q<4;++q) c[nf][q]=0.f;

        #pragma unroll
        for (int ks=0; ks<8; ++ks){
            const int kb = ks*8;
            uint32_t ahi[4], alo[4];
            {
                float x[4];
                x[0] = sQ[(g  )*SQ_STRIDE + kb+t  ];
                x[1] = sQ[(8+g)*SQ_STRIDE + kb+t  ];
                x[2] = sQ[(g  )*SQ_STRIDE + kb+t+4];
                x[3] = sQ[(8+g)*SQ_STRIDE + kb+t+4];
                split4(x, ahi, alo);
            }
            uint32_t bhi[2][2], blo[2][2];
            #pragma unroll
            for (int nf=0; nf<2; ++nf){
                const int cn = wid*16 + nf*8 + g;
                float y[2];
                y[0] = sKV[cn*SV_STRIDE + kb+t  ];
                y[1] = sKV[cn*SV_STRIDE + kb+t+4];
                split2(y, bhi[nf], blo[nf]);
            }
            #pragma unroll
            for (int nf=0; nf<2; ++nf){
                mma_tf32(c[nf], ahi, bhi[nf]);
                mma_tf32(c[nf], ahi, blo[nf]);
                mma_tf32(c[nf], alo, bhi[nf]);
            }
        }

        #pragma unroll
        for (int nf=0; nf<2; ++nf){
            const int jl = j0 + wid*16 + nf*8 + 2*t;
            const int gi0 = i0 + g, gi1 = gi0 + 8;
            float2 u0 = *(const float2*)(utT + ((long)b*S_ + gi0)*S_ + jl);
            float2 u1 = *(const float2*)(utT + ((long)b*S_ + gi1)*S_ + jl);
            float2 w0; w0.x = c[nf][0]*kscale*u0.x; w0.y = c[nf][1]*kscale*u0.y;
            float2 w1; w1.x = c[nf][2]*kscale*u1.x; w1.y = c[nf][3]*kscale*u1.y;
            *(float2*)(sS + g*SS_STRIDE + jl) = w0;
            *(float2*)(sS + (8+g)*SS_STRIDE + jl) = w1;
        }
    }
    __syncthreads();

    // ---- per-row softmax1 -> cumsum -> decay -> exp2 -> write g_p ----
    {
        const unsigned FULL = 0xffffffffu;
        const float gh = -log1pf(__expf(gammas[h]));

        #pragma unroll 1
        for (int q=0; q<2; ++q){
            int r  = wid*2 + q;
            int gi = i0 + r;
            int L  = gi + 1;
            float* row = sS + r*SS_STRIDE;
            float* prow = g_p + (bh*S_ + gi)*(long)S_;

            float mx = -1e30f;
            for (int j = lane; j < L; j += 32) mx = fmaxf(mx, row[j]);
            #pragma unroll
            for (int o=16;o>0;o>>=1) mx = fmaxf(mx, __shfl_xor_sync(FULL, mx, o));

            float sm = 0.f;
            for (int j = lane; j < L; j += 32) sm += __expf(row[j] - mx);
            #pragma unroll
            for (int o=16;o>0;o>>=1) sm += __shfl_xor_sync(FULL, sm, o);
            const float inv = 1.f / sm;

            float carry = 0.f, mx2 = -1e30f;
            int nch = (L + 31) >> 5;
            for (int c = 0; c < nch; ++c){
                int j = c*32 + lane;
                bool in = j < L;
                float s = in ? row[j] : 0.f;
                float e = in ? __expf(s - mx) : 0.f;
                float v = e;
                #pragma unroll
                for (int o=1;o<32;o<<=1){
                    float tt = __shfl_up_sync(FULL, v, o);
                    if (lane >= o) v += tt;
                }
                float cum = carry + v;
                carry += __shfl_sync(FULL, v, 31);
                if (in){
                    float rem = fmaxf(0.f, (sm - cum) * inv);
                    float pe  = fabsf((float)(gi - j));
                    float y   = rem * pe;
                    float dist = (y > 0.f) ? y * __frsqrt_rn(y) : 0.f;
                    float te = fmaxf(__expf(dist * gh), 1e-5f);
                    float s2 = s * te;
                    row[j] = s2;
                    mx2 = fmaxf(mx2, s2);
                }
            }
            #pragma unroll
            for (int o=16;o>0;o>>=1) mx2 = fmaxf(mx2, __shfl_xor_sync(FULL, mx2, o));

            float sm2 = 0.f;
            for (int j = lane; j < L; j += 32){
                float e2 = __expf(row[j] - mx2);
                prow[j] = e2;
                sm2 += e2;
            }
            // zero-pad to the 128-aligned boundary the PV kernel reads
            for (int j = L + lane; j < JZ; j += 32) prow[j] = 0.f;
            #pragma unroll
            for (int o=16;o>0;o>>=1) sm2 += __shfl_xor_sync(FULL, sm2, o);
            if (lane == 0) g_sinv[bh*S_ + gi] = 1.f / sm2;
        }
    }
}

// ---------------------------------------------------------------------------
// Kernel B: out[i][d] = sinv[i] * sum_j p[i][j] * v[j][d]  (tensor, 3xTF32)
// Block tile 128x64, causal k-range = (mt+1)*128; big tiles scheduled first.
// ---------------------------------------------------------------------------
#define SP_STRIDE 36
#define SVB_STRIDE 68
__global__ __launch_bounds__(256) void pv_kernel()
{
    __shared__ float sP[128*SP_STRIDE];
    __shared__ float sV[32*SVB_STRIDE];

    const int tid = threadIdx.x;
    const int wid = tid >> 5, lane = tid & 31;
    const int wm = wid & 3;
    const int wn = wid >> 2;
    const int g  = lane >> 2;
    const int t  = lane & 3;
    const int bh = blockIdx.y;
    const int b  = bh >> 3, h = bh & 7;
    const int mt = 7 - blockIdx.x;          // big tiles first
    const int m0 = mt * 128;
    const int KC = (mt + 1) * 4;            // k-chunks of 32

    const float* Pbase = g_p + (long)bh*S_*S_;
    const float* Vbase = g_v + (long)bh*S_*DK_;

    float c[2][4][4];
    #pragma unroll
    for (int mf=0; mf<2; ++mf)
        #pragma unroll
        for (int nf=0; nf<4; ++nf)
            #pragma unroll
            for (int q=0; q<4; ++q) c[mf][nf][q] = 0.f;

    for (int kc = 0; kc < KC; ++kc){
        const int k0 = kc * 32;
        __syncthreads();
        // P tile: 128 rows x 32
        #pragma unroll
        for (int it=0; it<4; ++it){
            int idx = tid + it*256;
            int row = idx >> 3, c4 = (idx & 7)*4;
            float4 v = *(const float4*)(Pbase + (long)(m0+row)*S_ + k0 + c4);
            *(float4*)(sP + row*SP_STRIDE + c4) = v;
        }
        // V tile: 32 rows x 64, kept [k][d]
        #pragma unroll
        for (int it=0; it<2; ++it){
            int idx = tid + it*256;
            int row = idx >> 4, c4 = (idx & 15)*4;
            float4 v = *(const float4*)(Vbase + (long)(k0+row)*DK_ + c4);
            *(float4*)(sV + row*SVB_STRIDE + c4) = v;
        }
        __syncthreads();

        #pragma unroll
        for (int ks=0; ks<4; ++ks){
            const int kb = ks*8;
            uint32_t ahi[2][4], alo[2][4];
            #pragma unroll
            for (int mf=0; mf<2; ++mf){
                const int ra = wm*32 + mf*16;
                float x[4];
                x[0] = sP[(ra+g  )*SP_STRIDE + kb+t  ];
                x[1] = sP[(ra+8+g)*SP_STRIDE + kb+t  ];
                x[2] = sP[(ra+g  )*SP_STRIDE + kb+t+4];
                x[3] = sP[(ra+8+g)*SP_STRIDE + kb+t+4];
                split4(x, ahi[mf], alo[mf]);
            }
            uint32_t vhi[4][2], vlo[4][2];
            #pragma unroll
            for (int nf=0; nf<4; ++nf){
                const int cn = wn*32 + nf*8 + g;
                float y[2];
                y[0] = sV[(kb+t  )*SVB_STRIDE + cn];
                y[1] = sV[(kb+t+4)*SVB_STRIDE + cn];
                split2(y, vhi[nf], vlo[nf]);
            }
            #pragma unroll
            for (int mf=0; mf<2; ++mf)
                #pragma unroll
                for (int nf=0; nf<4; ++nf){
                    mma_tf32(c[mf][nf], ahi[mf], vhi[nf]);
                    mma_tf32(c[mf][nf], ahi[mf], vlo[nf]);
                    mma_tf32(c[mf][nf], alo[mf], vhi[nf]);
                }
        }
    }

    // epilogue: scale by sinv, scatter head-split
    #pragma unroll
    for (int mf=0; mf<2; ++mf){
        const int row0 = m0 + wm*32 + mf*16 + g;
        float sc0 = g_sinv[(long)bh*S_ + row0];
        float sc1 = g_sinv[(long)bh*S_ + row0 + 8];
        #pragma unroll
        for (int nf=0; nf<4; ++nf){
            const int ncol = wn*32 + nf*8 + 2*t;
            float2 v0; v0.x = c[mf][nf][0]*sc0; v0.y = c[mf][nf][1]*sc0;
            float2 v1; v1.x = c[mf][nf][2]*sc1; v1.y = c[mf][nf][3]*sc1;
            *(float2*)(g_attn + ((long)b*S_ + row0)*D_ + h*DK_ + ncol) = v0;
            *(float2*)(g_attn + ((long)b*S_ + row0 + 8)*D_ + h*DK_ + ncol) = v1;
        }
    }
}

// ---------------------------------------------------------------------------
extern "C" void kernel_launch(void* const* d_in, const int* in_sizes, int n_in,
                              void* d_out, int out_size)
{
    const float* x      = (const float*)d_in[0];
    const float* utT    = (const float*)d_in[1];
    const float* Wk     = (const float*)d_in[2];
    const float* bk     = (const float*)d_in[3];
    const float* Wv     = (const float*)d_in[4];
    const float* bv     = (const float*)d_in[5];
    const float* Wo     = (const float*)d_in[6];
    const float* bo     = (const float*)d_in[7];
    const float* gammas = (const float*)d_in[8];
    float* out = (float*)d_out;

    float* qk; cudaGetSymbolAddress((void**)&qk, g_qk);
    float* vv; cudaGetSymbolAddress((void**)&vv, g_v);
    float* at; cudaGetSymbolAddress((void**)&at, g_attn);

    dim3 tg(D_/64, (B_*S_)/128);   // 8 x 64

    // QK + V projections on tensor cores (3xTF32)
    gemm_mma<<<tg, 256>>>(x, Wk, bk, qk, 1);
    gemm_mma<<<tg, 256>>>(x, Wv, bv, vv, 1);

    // attention: score+softmax kernel, then PV GEMM kernel
    size_t smem_bytes = (size_t)(TM*SS_STRIDE + TM*SQ_STRIDE + KVBUF) * sizeof(float);
    cudaFuncSetAttribute(score_kernel, cudaFuncAttributeMaxDynamicSharedMemorySize, (int)smem_bytes);
    score_kernel<<<dim3(S_/TM, H_, B_), 256, smem_bytes>>>(utT, gammas);
    pv_kernel<<<dim3(S_/128, B_*H_), 256>>>();

    // output projection on tensor cores
    gemm_mma<<<tg, 256>>>(at, Wo, bo, out, 0);
}